// round 7
// baseline (speedup 1.0000x reference)
#include <cuda_runtime.h>
#include <cstdint>

#define T_STEPS 128
#define BATCH   64
#define VDIM    2048
#define HDIM    1024
#define GDIM    4096   // 4*H

#define NCTA    128    // persistent CTAs (one per 8 hidden units)
#define NTHR    128    // 4 warps

// ---------------- scratch (static device globals; no allocation) ----------
__device__ float g_gates[(size_t)T_STEPS * BATCH * GDIM];  // 134 MB: x@Wi + b
__device__ float g_h[2][BATCH * HDIM];
__device__ float g_c[2][BATCH * HDIM];
__device__ int   g_eos[2][BATCH];
__device__ unsigned g_bar_count;
__device__ volatile unsigned g_bar_gen;

// ---------------- helpers ------------------------------------------------
__device__ __forceinline__ uint32_t f2tf32(float f) {
    uint32_t r;
    asm("cvt.rna.tf32.f32 %0, %1;" : "=r"(r) : "f"(f));
    return r;
}

__device__ __forceinline__ void st_tf32_4(uint32_t* d, float4 v) {
    uint4 u;
    u.x = f2tf32(v.x); u.y = f2tf32(v.y); u.z = f2tf32(v.z); u.w = f2tf32(v.w);
    *(uint4*)d = u;
}

__device__ __forceinline__ void mma_tf32(float c[4],
                                         uint32_t a0, uint32_t a1, uint32_t a2, uint32_t a3,
                                         uint32_t b0, uint32_t b1) {
    asm volatile(
        "mma.sync.aligned.m16n8k8.row.col.f32.tf32.tf32.f32 "
        "{%0,%1,%2,%3}, {%4,%5,%6,%7}, {%8,%9}, {%0,%1,%2,%3};\n"
        : "+f"(c[0]), "+f"(c[1]), "+f"(c[2]), "+f"(c[3])
        : "r"(a0), "r"(a1), "r"(a2), "r"(a3), "r"(b0), "r"(b1));
}

__device__ __forceinline__ float sigf(float x) {
    return 1.0f / (1.0f + expf(-x));
}

__device__ __forceinline__ float4 ldcg4(const float* p) {
    return __ldcg((const float4*)p);
}

// ---------------- init state ---------------------------------------------
__global__ void init_state(const float* __restrict__ c0,
                           const float* __restrict__ h0,
                           const unsigned char* __restrict__ eos0) {
    int i = blockIdx.x * blockDim.x + threadIdx.x;
    if (i < BATCH * HDIM) {
        g_c[0][i] = c0[i];
        g_h[0][i] = h0[i];
    }
    if (i < BATCH) g_eos[0][i] = eos0[i] ? 1 : 0;
    if (i == 0) { g_bar_count = 0; g_bar_gen = 0; }
}

// ---------------- smem layout for the fused kernel -------------------------
// [ws: Wh slice][hs: h tile dbl][As: gemm A dbl][Bs: gemm B dbl]
#define WS_STR 36
#define HS_STR 36
#define WS_WORDS (HDIM * WS_STR)            // 36864
#define HS_WORDS (2 * BATCH * HS_STR)       // 4608

#define GT_BM 128
#define GT_BN 64
#define GT_BK 16
#define GT_ASTR 20
#define GT_BSTR 68
#define AS_WORDS (2 * GT_BM * GT_ASTR)      // 5120
#define BS_WORDS (2 * GT_BK * GT_BSTR)      // 2176
#define PSMEM_BYTES ((WS_WORDS + HS_WORDS + AS_WORDS + BS_WORDS) * 4)  // 195072

#define N_SLOTS 32   // 64 by-rows x 64 bx-cols tiles / 128 CTAs

__device__ __forceinline__ void grid_barrier() {
    __syncthreads();
    if (threadIdx.x == 0) {
        __threadfence();
        unsigned gen = g_bar_gen;
        unsigned t = atomicAdd(&g_bar_count, 1u);
        if (t == NCTA - 1) {
            g_bar_count = 0;
            __threadfence();
            g_bar_gen = gen + 1;
        } else {
            while (g_bar_gen == gen) { }
            __threadfence();
        }
    }
    __syncthreads();
}

// ---- one gates tile: g_gates[m0:m0+128, n0:n0+64] = X@Wi + b --------------
// 4 warps, warp tile 32x64 (identical math to the proven gemm1, wn=0).
__device__ __forceinline__ void gemm_slot(int s, const float* __restrict__ X,
                                          const float* __restrict__ Wi,
                                          const float* __restrict__ bias,
                                          uint32_t* As, uint32_t* Bs,
                                          int tid, int w, int lq, int lr) {
    const int gtid = s * NCTA + blockIdx.x;
    const int by = gtid >> 6;            // 0..63
    const int bx = gtid & 63;            // 0..63
    const int m0 = by * GT_BM;
    const int n0 = bx * GT_BN;
    const int wm = w * 32;

    float acc[2][8][4];
#pragma unroll
    for (int mi = 0; mi < 2; mi++)
#pragma unroll
        for (int ni = 0; ni < 8; ni++)
#pragma unroll
            for (int q = 0; q < 4; q++) acc[mi][ni][q] = 0.0f;

    // loaders: A row = tid (16 k-cols, 4xfloat4); B row = tid>>3, 8 cols
    const int ar   = tid;
    const int brow = tid >> 3;
    const int bcol = (tid & 7) * 8;

    const float* asrc = X  + (size_t)(m0 + ar) * VDIM;
    const float* bsrc = Wi + (size_t)brow * GDIM + n0 + bcol;

    float4 av[4], bv[2];
#pragma unroll
    for (int v = 0; v < 4; v++) av[v] = *(const float4*)(asrc + v * 4);
    bv[0] = *(const float4*)(bsrc);
    bv[1] = *(const float4*)(bsrc + 4);

    const int NIT = VDIM / GT_BK;   // 128
    for (int it = 0; it < NIT; it++) {
        const int p = it & 1;
        uint32_t* Ab = As + p * (GT_BM * GT_ASTR);
        uint32_t* Bb = Bs + p * (GT_BK * GT_BSTR);
#pragma unroll
        for (int v = 0; v < 4; v++)
            st_tf32_4(Ab + ar * GT_ASTR + v * 4, av[v]);
        st_tf32_4(Bb + brow * GT_BSTR + bcol,     bv[0]);
        st_tf32_4(Bb + brow * GT_BSTR + bcol + 4, bv[1]);
        __syncthreads();

        if (it + 1 < NIT) {
            int k1 = (it + 1) * GT_BK;
#pragma unroll
            for (int v = 0; v < 4; v++) av[v] = *(const float4*)(asrc + k1 + v * 4);
            bv[0] = *(const float4*)(bsrc + (size_t)k1 * GDIM);
            bv[1] = *(const float4*)(bsrc + (size_t)k1 * GDIM + 4);
        }

#pragma unroll
        for (int kk = 0; kk < GT_BK; kk += 8) {
            uint32_t afr[2][4];
#pragma unroll
            for (int mi = 0; mi < 2; mi++) {
                int r = wm + mi * 16 + lq;
                afr[mi][0] = Ab[r * GT_ASTR + kk + lr];
                afr[mi][1] = Ab[(r + 8) * GT_ASTR + kk + lr];
                afr[mi][2] = Ab[r * GT_ASTR + kk + lr + 4];
                afr[mi][3] = Ab[(r + 8) * GT_ASTR + kk + lr + 4];
            }
            uint32_t bfr[8][2];
#pragma unroll
            for (int ni = 0; ni < 8; ni++) {
                int c = ni * 8 + lq;
                bfr[ni][0] = Bb[(kk + lr) * GT_BSTR + c];
                bfr[ni][1] = Bb[(kk + lr + 4) * GT_BSTR + c];
            }
#pragma unroll
            for (int mi = 0; mi < 2; mi++)
#pragma unroll
                for (int ni = 0; ni < 8; ni++)
                    mma_tf32(acc[mi][ni], afr[mi][0], afr[mi][1], afr[mi][2], afr[mi][3],
                             bfr[ni][0], bfr[ni][1]);
        }
        __syncthreads();   // protect buffer reuse across slot boundaries too
    }

#pragma unroll
    for (int mi = 0; mi < 2; mi++) {
#pragma unroll
        for (int ni = 0; ni < 8; ni++) {
            int r0 = m0 + wm + mi * 16 + lq;
            int c0 = n0 + ni * 8 + 2 * lr;
            float bl = bias[c0];
            float bh = bias[c0 + 1];
            g_gates[(size_t)r0 * GDIM + c0]           = acc[mi][ni][0] + bl;
            g_gates[(size_t)r0 * GDIM + c0 + 1]       = acc[mi][ni][1] + bh;
            g_gates[(size_t)(r0 + 8) * GDIM + c0]     = acc[mi][ni][2] + bl;
            g_gates[(size_t)(r0 + 8) * GDIM + c0 + 1] = acc[mi][ni][3] + bh;
        }
    }
}

// ---------------- fused persistent kernel ----------------------------------
// Recurrence identical to round 4; gates production folded in as slot tiles:
// slot 0 in prologue, slot s during step s (s=1..31). Grid barrier orders all.
__global__ __launch_bounds__(NTHR) void lstm_fused(const float* __restrict__ X,
                                                   const float* __restrict__ Wi,
                                                   const float* __restrict__ Wh,
                                                   const float* __restrict__ bias,
                                                   float* __restrict__ ys) {
    extern __shared__ uint32_t dsm[];
    uint32_t* ws = dsm;                              // [1024][36] Wh (tf32)
    uint32_t* hs = dsm + WS_WORDS;                   // [2][64][36] h tiles
    uint32_t* As = dsm + WS_WORDS + HS_WORDS;        // gemm A dbl
    uint32_t* Bs = As + AS_WORDS;                    // gemm B dbl

    const int tid  = threadIdx.x;
    const int lane = tid & 31;
    const int w    = tid >> 5;       // warp 0..3
    const int lq   = lane >> 2;
    const int lr   = lane & 3;
    const int j    = blockIdx.x;     // hidden slice

    // ---- preload Wh slice into SMEM once (converted to tf32) ----
    {
        const int wk = tid >> 2;     // 0..31
        const int wg = tid & 3;      // gate 0..3
        for (int base = 0; base < HDIM; base += 32) {
            const float4* wsrc = (const float4*)(Wh + (size_t)(base + wk) * GDIM + wg * HDIM + j * 8);
            st_tf32_4(ws + (base + wk) * WS_STR + wg * 8,     wsrc[0]);
            st_tf32_4(ws + (base + wk) * WS_STR + wg * 8 + 4, wsrc[1]);
        }
    }
    __syncthreads();

    // ---- prologue: slot 0 (gates for steps 0..3), then global sync ----
    gemm_slot(0, X, Wi, bias, As, Bs, tid, w, lq, lr);
    __threadfence();
    grid_barrier();

    const int hr = tid >> 1;         // 0..63 (h tile row)
    const int hc = (tid & 1) * 16;   // 0 or 16

    for (int t = 0; t < T_STEPS; t++) {
        const int cur = t & 1;
        const int nxt = cur ^ 1;
        const float* hprev = g_h[cur];
        const float* cprev = g_c[cur];
        float* hnex = g_h[nxt];
        float* cnex = g_c[nxt];

        float acc[4][4];
#pragma unroll
        for (int g = 0; g < 4; g++)
#pragma unroll
            for (int q = 0; q < 4; q++) acc[g][q] = 0.0f;

        // preload tile 0 into registers (.cg: L1 may hold stale state data)
        float4 rv[4];
#pragma unroll
        for (int v = 0; v < 4; v++)
            rv[v] = ldcg4(hprev + (size_t)hr * HDIM + hc + v * 4);

        for (int it = 0; it < HDIM / 32; it++) {
            uint32_t* hb = hs + (it & 1) * (BATCH * HS_STR);
#pragma unroll
            for (int v = 0; v < 4; v++)
                st_tf32_4(hb + hr * HS_STR + hc + v * 4, rv[v]);
            __syncthreads();

            if (it + 1 < HDIM / 32) {
                int k1 = (it + 1) * 32;
#pragma unroll
                for (int v = 0; v < 4; v++)
                    rv[v] = ldcg4(hprev + (size_t)hr * HDIM + k1 + hc + v * 4);
            }

            const int k0 = it * 32;
#pragma unroll
            for (int kk = 0; kk < 32; kk += 8) {
                int r = w * 16 + lq;
                uint32_t a0 = hb[r * HS_STR + kk + lr];
                uint32_t a1 = hb[(r + 8) * HS_STR + kk + lr];
                uint32_t a2 = hb[r * HS_STR + kk + lr + 4];
                uint32_t a3 = hb[(r + 8) * HS_STR + kk + lr + 4];
#pragma unroll
                for (int g = 0; g < 4; g++) {
                    uint32_t b0 = ws[(k0 + kk + lr) * WS_STR + g * 8 + lq];
                    uint32_t b1 = ws[(k0 + kk + lr + 4) * WS_STR + g * 8 + lq];
                    mma_tf32(acc[g], a0, a1, a2, a3, b0, b1);
                }
            }
        }

        // ---- elementwise LSTM cell (round-4 exact) ----
        const float* gx = g_gates + (size_t)t * BATCH * GDIM;

#pragma unroll
        for (int half = 0; half < 2; half++) {
            int r = w * 16 + lq + half * 8;
            bool m = (__ldcg(&g_eos[cur][r]) != 0);
#pragma unroll
            for (int cc = 0; cc < 2; cc++) {
                int ci   = half * 2 + cc;
                int hcol = j * 8 + 2 * lr + cc;
                float iv = acc[0][ci] + __ldg(gx + (size_t)r * GDIM + hcol);
                float fv = acc[1][ci] + __ldg(gx + (size_t)r * GDIM + HDIM + hcol);
                float gv = acc[2][ci] + __ldg(gx + (size_t)r * GDIM + 2 * HDIM + hcol);
                float ov = acc[3][ci] + __ldg(gx + (size_t)r * GDIM + 3 * HDIM + hcol);

                float cp  = __ldcg(cprev + (size_t)r * HDIM + hcol);
                float ncv = sigf(fv) * cp + sigf(iv) * tanhf(gv);
                float nhv = sigf(ov) * tanhf(ncv);

                ys[((size_t)t * BATCH + r) * HDIM + hcol] = nhv;   // unmasked
                cnex[(size_t)r * HDIM + hcol] = m ? cp : ncv;
                hnex[(size_t)r * HDIM + hcol] = m ? __ldcg(hprev + (size_t)r * HDIM + hcol) : nhv;
            }
        }

        if (blockIdx.x == 0 && tid < BATCH) {
            float xe = __ldg(X + ((size_t)t * BATCH + tid) * VDIM + 1);
            int eo = __ldcg(&g_eos[cur][tid]);
            g_eos[nxt][tid] = (eo != 0 || xe != 0.0f) ? 1 : 0;
        }

        // ---- gates production: slot t (covers steps 4t..4t+3, needed later)
        if (t >= 1 && t < N_SLOTS)
            gemm_slot(t, X, Wi, bias, As, Bs, tid, w, lq, lr);

        __threadfence();
        grid_barrier();
    }
}

// ---------------- launch ---------------------------------------------------
extern "C" void kernel_launch(void* const* d_in, const int* in_sizes, int n_in,
                              void* d_out, int out_size) {
    const float* x  = (const float*)d_in[0];
    const float* Wi = (const float*)d_in[1];
    const float* Wh = (const float*)d_in[2];
    const float* b  = (const float*)d_in[3];
    const float* c0 = (const float*)d_in[4];
    const float* h0 = (const float*)d_in[5];
    const unsigned char* eos0 = (const unsigned char*)d_in[6];
    float* ys = (float*)d_out;

    static bool attr_done = false;
    if (!attr_done) {
        cudaFuncSetAttribute(lstm_fused,
                             cudaFuncAttributeMaxDynamicSharedMemorySize, PSMEM_BYTES);
        attr_done = true;
    }

    init_state<<<(BATCH * HDIM + 255) / 256, 256>>>(c0, h0, eos0);
    lstm_fused<<<NCTA, NTHR, PSMEM_BYTES>>>(x, Wi, Wh, b, ys);
}

// round 8
// speedup vs baseline: 1.6950x; 1.6950x over previous
#include <cuda_runtime.h>
#include <cstdint>

#define T_STEPS 128
#define BATCH   64
#define VDIM    2048
#define HDIM    1024
#define GDIM    4096   // 4*H

#define NCTA    128    // persistent CTAs (one per 8 hidden units)
#define NTHR    128    // 4 warps

// ---------------- scratch (static device globals; no allocation) ----------
__device__ float g_gates[(size_t)T_STEPS * BATCH * GDIM];  // 134 MB: x@Wi + b
__device__ float g_h[2][BATCH * HDIM];
__device__ float g_c[2][BATCH * HDIM];
__device__ int   g_eos[2][BATCH];
__device__ unsigned g_bar_count;
__device__ volatile unsigned g_bar_gen;

// ---------------- helpers ------------------------------------------------
__device__ __forceinline__ uint32_t f2tf32(float f) {
    uint32_t r;
    asm("cvt.rna.tf32.f32 %0, %1;" : "=r"(r) : "f"(f));
    return r;
}

__device__ __forceinline__ void st_tf32_4(uint32_t* d, float4 v) {
    uint4 u;
    u.x = f2tf32(v.x); u.y = f2tf32(v.y); u.z = f2tf32(v.z); u.w = f2tf32(v.w);
    *(uint4*)d = u;
}

__device__ __forceinline__ void mma_tf32(float c[4],
                                         uint32_t a0, uint32_t a1, uint32_t a2, uint32_t a3,
                                         uint32_t b0, uint32_t b1) {
    asm volatile(
        "mma.sync.aligned.m16n8k8.row.col.f32.tf32.tf32.f32 "
        "{%0,%1,%2,%3}, {%4,%5,%6,%7}, {%8,%9}, {%0,%1,%2,%3};\n"
        : "+f"(c[0]), "+f"(c[1]), "+f"(c[2]), "+f"(c[3])
        : "r"(a0), "r"(a1), "r"(a2), "r"(a3), "r"(b0), "r"(b1));
}

__device__ __forceinline__ float sigf(float x) {
    return 1.0f / (1.0f + expf(-x));
}

__device__ __forceinline__ void cpa16(void* dst_smem, const void* src_glob) {
    uint32_t d = (uint32_t)__cvta_generic_to_shared(dst_smem);
    asm volatile("cp.async.cg.shared.global [%0], [%1], 16;\n" :: "r"(d), "l"(src_glob));
}
#define CP_COMMIT() asm volatile("cp.async.commit_group;\n" ::: "memory")
#define CP_WAIT1()  asm volatile("cp.async.wait_group 1;\n" ::: "memory")

// ---------------- init state ---------------------------------------------
__global__ void init_state(const float* __restrict__ c0,
                           const float* __restrict__ h0,
                           const unsigned char* __restrict__ eos0) {
    int i = blockIdx.x * blockDim.x + threadIdx.x;
    if (i < BATCH * HDIM) {
        g_c[0][i] = c0[i];
        g_h[0][i] = h0[i];
    }
    if (i < BATCH) g_eos[0][i] = eos0[i] ? 1 : 0;
    if (i == 0) { g_bar_count = 0; g_bar_gen = 0; }
}

// ---------------- phase 1: gates_x = X @ Wi + b  (round-4 proven) ----------
#define G1_BM 128
#define G1_BN 128
#define G1_BK 16
#define G1_ASTR 20
#define G1_BSTR 132

__global__ __launch_bounds__(256) void gemm1(const float* __restrict__ X,
                                             const float* __restrict__ Wi,
                                             const float* __restrict__ bias) {
    __shared__ uint32_t As[2][G1_BM * G1_ASTR];
    __shared__ uint32_t Bs[2][G1_BK * G1_BSTR];

    const int tid  = threadIdx.x;
    const int lane = tid & 31;
    const int wid  = tid >> 5;
    const int wm   = (wid >> 1) * 32;
    const int wn   = (wid & 1) * 64;
    const int lq   = lane >> 2;
    const int lr   = lane & 3;

    const int m0 = blockIdx.y * G1_BM;
    const int n0 = blockIdx.x * G1_BN;

    float acc[2][8][4];
#pragma unroll
    for (int mi = 0; mi < 2; mi++)
#pragma unroll
        for (int ni = 0; ni < 8; ni++)
#pragma unroll
            for (int q = 0; q < 4; q++) acc[mi][ni][q] = 0.0f;

    const int ar = tid >> 1;
    const int ac = (tid & 1) * 8;
    const int br = tid >> 4;
    const int bc = (tid & 15) * 8;

    const float* asrc = X  + (size_t)(m0 + ar) * VDIM + ac;
    const float* bsrc = Wi + (size_t)br * GDIM + n0 + bc;

    float4 av0 = *(const float4*)(asrc);
    float4 av1 = *(const float4*)(asrc + 4);
    float4 bv0 = *(const float4*)(bsrc);
    float4 bv1 = *(const float4*)(bsrc + 4);

    const int NIT = VDIM / G1_BK;   // 128
    for (int it = 0; it < NIT; it++) {
        const int p = it & 1;
        st_tf32_4(&As[p][ar * G1_ASTR + ac],     av0);
        st_tf32_4(&As[p][ar * G1_ASTR + ac + 4], av1);
        st_tf32_4(&Bs[p][br * G1_BSTR + bc],     bv0);
        st_tf32_4(&Bs[p][br * G1_BSTR + bc + 4], bv1);
        __syncthreads();

        if (it + 1 < NIT) {
            int k1 = (it + 1) * G1_BK;
            av0 = *(const float4*)(asrc + k1);
            av1 = *(const float4*)(asrc + k1 + 4);
            bv0 = *(const float4*)(bsrc + (size_t)k1 * GDIM);
            bv1 = *(const float4*)(bsrc + (size_t)k1 * GDIM + 4);
        }

        const uint32_t* as = As[p];
        const uint32_t* bs = Bs[p];
#pragma unroll
        for (int kk = 0; kk < G1_BK; kk += 8) {
            uint32_t afr[2][4];
#pragma unroll
            for (int mi = 0; mi < 2; mi++) {
                int r = wm + mi * 16 + lq;
                afr[mi][0] = as[r * G1_ASTR + kk + lr];
                afr[mi][1] = as[(r + 8) * G1_ASTR + kk + lr];
                afr[mi][2] = as[r * G1_ASTR + kk + lr + 4];
                afr[mi][3] = as[(r + 8) * G1_ASTR + kk + lr + 4];
            }
            uint32_t bfr[8][2];
#pragma unroll
            for (int ni = 0; ni < 8; ni++) {
                int c = wn + ni * 8 + lq;
                bfr[ni][0] = bs[(kk + lr) * G1_BSTR + c];
                bfr[ni][1] = bs[(kk + lr + 4) * G1_BSTR + c];
            }
#pragma unroll
            for (int mi = 0; mi < 2; mi++)
#pragma unroll
                for (int ni = 0; ni < 8; ni++)
                    mma_tf32(acc[mi][ni], afr[mi][0], afr[mi][1], afr[mi][2], afr[mi][3],
                             bfr[ni][0], bfr[ni][1]);
        }
    }

#pragma unroll
    for (int mi = 0; mi < 2; mi++) {
#pragma unroll
        for (int ni = 0; ni < 8; ni++) {
            int r0 = m0 + wm + mi * 16 + lq;
            int c0 = n0 + wn + ni * 8 + 2 * lr;
            float bl = bias[c0];
            float bh = bias[c0 + 1];
            g_gates[(size_t)r0 * GDIM + c0]           = acc[mi][ni][0] + bl;
            g_gates[(size_t)r0 * GDIM + c0 + 1]       = acc[mi][ni][1] + bh;
            g_gates[(size_t)(r0 + 8) * GDIM + c0]     = acc[mi][ni][2] + bl;
            g_gates[(size_t)(r0 + 8) * GDIM + c0 + 1] = acc[mi][ni][3] + bh;
        }
    }
}

// ---------------- phase 2: persistent recurrent kernel ---------------------
// Round-4 structure; ONLY change: h tiles staged via a 3-stage cp.async.cg
// pipeline (float in smem, tf32 convert at consume). One commit per iter,
// empty groups included, so wait_group 1 semantics are uniform.
#define NSTG 3
#define WS_STR 36
#define HS_STR 36
#define WS_WORDS (HDIM * WS_STR)                // 36864
#define HS_WORDS (NSTG * BATCH * HS_STR)        // 6912
#define PSMEM_BYTES ((WS_WORDS + HS_WORDS) * 4) // 175104 B

__device__ __forceinline__ void grid_barrier() {
    __syncthreads();
    if (threadIdx.x == 0) {
        __threadfence();
        unsigned gen = g_bar_gen;
        unsigned t = atomicAdd(&g_bar_count, 1u);
        if (t == NCTA - 1) {
            g_bar_count = 0;
            __threadfence();
            g_bar_gen = gen + 1;
        } else {
            while (g_bar_gen == gen) { }
            __threadfence();
        }
    }
    __syncthreads();
}

__global__ __launch_bounds__(NTHR) void lstm_persist(const float* __restrict__ X,
                                                     const float* __restrict__ Wh,
                                                     float* __restrict__ ys) {
    extern __shared__ uint32_t dsm[];
    uint32_t* ws = dsm;                       // [1024][36] Wh slice (tf32)
    float*    hs = (float*)(dsm + WS_WORDS);  // [3][64][36] h tiles (float)

    const int tid  = threadIdx.x;
    const int lane = tid & 31;
    const int w    = tid >> 5;       // warp 0..3 -> batch rows w*16..
    const int lq   = lane >> 2;
    const int lr   = lane & 3;
    const int j    = blockIdx.x;     // hidden slice

    // ---- preload Wh slice into SMEM once (converted to tf32) ----
    {
        const int wk = tid >> 2;     // 0..31
        const int wg = tid & 3;      // gate 0..3
        for (int base = 0; base < HDIM; base += 32) {
            const float4* wsrc = (const float4*)(Wh + (size_t)(base + wk) * GDIM + wg * HDIM + j * 8);
            st_tf32_4(ws + (base + wk) * WS_STR + wg * 8,     wsrc[0]);
            st_tf32_4(ws + (base + wk) * WS_STR + wg * 8 + 4, wsrc[1]);
        }
    }
    __syncthreads();

    const int hr = tid >> 1;         // 0..63 (h tile row)
    const int hc = (tid & 1) * 16;   // 0 or 16
    const int NIT = HDIM / 32;       // 32 k-tiles per step

    for (int t = 0; t < T_STEPS; t++) {
        const int cur = t & 1;
        const int nxt = cur ^ 1;
        const float* hprev = g_h[cur];
        const float* cprev = g_c[cur];
        float* hnex = g_h[nxt];
        float* cnex = g_c[nxt];

        float acc[4][4];
#pragma unroll
        for (int g = 0; g < 4; g++)
#pragma unroll
            for (int q = 0; q < 4; q++) acc[g][q] = 0.0f;

        // ---- cp.async pipeline prologue: stages 0 and 1 (one group each) --
#pragma unroll
        for (int s = 0; s < 2; s++) {
            float* hb = hs + s * (BATCH * HS_STR);
#pragma unroll
            for (int v = 0; v < 4; v++)
                cpa16(hb + hr * HS_STR + hc + v * 4,
                      hprev + (size_t)hr * HDIM + s * 32 + hc + v * 4);
            CP_COMMIT();
        }

        for (int it = 0; it < NIT; it++) {
            CP_WAIT1();          // oldest pending group (stage it) complete
            __syncthreads();     // make it visible to all threads

            // issue stage it+2 (or nothing) — exactly one commit per iter
            if (it + 2 < NIT) {
                float* hb2 = hs + ((it + 2) % NSTG) * (BATCH * HS_STR);
#pragma unroll
                for (int v = 0; v < 4; v++)
                    cpa16(hb2 + hr * HS_STR + hc + v * 4,
                          hprev + (size_t)hr * HDIM + (it + 2) * 32 + hc + v * 4);
            }
            CP_COMMIT();

            const float* hb = hs + (it % NSTG) * (BATCH * HS_STR);
            const int k0 = it * 32;
#pragma unroll
            for (int kk = 0; kk < 32; kk += 8) {
                int r = w * 16 + lq;
                uint32_t a0 = f2tf32(hb[r * HS_STR + kk + lr]);
                uint32_t a1 = f2tf32(hb[(r + 8) * HS_STR + kk + lr]);
                uint32_t a2 = f2tf32(hb[r * HS_STR + kk + lr + 4]);
                uint32_t a3 = f2tf32(hb[(r + 8) * HS_STR + kk + lr + 4]);
#pragma unroll
                for (int g = 0; g < 4; g++) {
                    uint32_t b0 = ws[(k0 + kk + lr) * WS_STR + g * 8 + lq];
                    uint32_t b1 = ws[(k0 + kk + lr + 4) * WS_STR + g * 8 + lq];
                    mma_tf32(acc[g], a0, a1, a2, a3, b0, b1);
                }
            }
            // no trailing sync: stage (it+2)%NSTG written next iter was last
            // consumed at iter it-1, and every thread passed sync(it) after
            // finishing compute(it-1).
        }

        // ---- elementwise LSTM cell (round-4 exact) ----
        const float* gx = g_gates + (size_t)t * BATCH * GDIM;

#pragma unroll
        for (int half = 0; half < 2; half++) {
            int r = w * 16 + lq + half * 8;
            bool m = (__ldcg(&g_eos[cur][r]) != 0);
#pragma unroll
            for (int cc = 0; cc < 2; cc++) {
                int ci   = half * 2 + cc;
                int hcol = j * 8 + 2 * lr + cc;
                float iv = acc[0][ci] + __ldg(gx + (size_t)r * GDIM + hcol);
                float fv = acc[1][ci] + __ldg(gx + (size_t)r * GDIM + HDIM + hcol);
                float gv = acc[2][ci] + __ldg(gx + (size_t)r * GDIM + 2 * HDIM + hcol);
                float ov = acc[3][ci] + __ldg(gx + (size_t)r * GDIM + 3 * HDIM + hcol);

                float cp  = __ldcg(cprev + (size_t)r * HDIM + hcol);
                float ncv = sigf(fv) * cp + sigf(iv) * tanhf(gv);
                float nhv = sigf(ov) * tanhf(ncv);

                ys[((size_t)t * BATCH + r) * HDIM + hcol] = nhv;   // unmasked
                cnex[(size_t)r * HDIM + hcol] = m ? cp : ncv;
                hnex[(size_t)r * HDIM + hcol] = m ? __ldcg(hprev + (size_t)r * HDIM + hcol) : nhv;
            }
        }

        if (blockIdx.x == 0 && tid < BATCH) {
            float xe = __ldg(X + ((size_t)t * BATCH + tid) * VDIM + 1);
            int eo = __ldcg(&g_eos[cur][tid]);
            g_eos[nxt][tid] = (eo != 0 || xe != 0.0f) ? 1 : 0;
        }

        __threadfence();
        grid_barrier();
    }
}

// ---------------- launch ---------------------------------------------------
extern "C" void kernel_launch(void* const* d_in, const int* in_sizes, int n_in,
                              void* d_out, int out_size) {
    const float* x  = (const float*)d_in[0];
    const float* Wi = (const float*)d_in[1];
    const float* Wh = (const float*)d_in[2];
    const float* b  = (const float*)d_in[3];
    const float* c0 = (const float*)d_in[4];
    const float* h0 = (const float*)d_in[5];
    const unsigned char* eos0 = (const unsigned char*)d_in[6];
    float* ys = (float*)d_out;

    static bool attr_done = false;
    if (!attr_done) {
        cudaFuncSetAttribute(lstm_persist,
                             cudaFuncAttributeMaxDynamicSharedMemorySize, PSMEM_BYTES);
        attr_done = true;
    }

    init_state<<<(BATCH * HDIM + 255) / 256, 256>>>(c0, h0, eos0);

    dim3 g1(GDIM / G1_BN, (T_STEPS * BATCH) / G1_BM);   // 32 x 64
    gemm1<<<g1, 256>>>(x, Wi, b);

    lstm_persist<<<NCTA, NTHR, PSMEM_BYTES>>>(x, Wh, ys);
}

// round 9
// speedup vs baseline: 1.9068x; 1.1250x over previous
#include <cuda_runtime.h>
#include <cstdint>

#define T_STEPS 128
#define BATCH   64
#define VDIM    2048
#define HDIM    1024
#define GDIM    4096   // 4*H

#define NCTA    128    // persistent CTAs (one per 8 hidden units)
#define NTHR    256    // 8 warps: 4 (M) x 2 (N/gate-pair)

// ---------------- scratch (static device globals; no allocation) ----------
__device__ float g_gates[(size_t)T_STEPS * BATCH * GDIM];  // 134 MB: x@Wi + b
__device__ float g_h[2][BATCH * HDIM];
__device__ float g_c[2][BATCH * HDIM];
__device__ int   g_eos[2][BATCH];
__device__ unsigned g_bar_count;
__device__ volatile unsigned g_bar_gen;

// ---------------- helpers ------------------------------------------------
__device__ __forceinline__ uint32_t f2tf32(float f) {
    uint32_t r;
    asm("cvt.rna.tf32.f32 %0, %1;" : "=r"(r) : "f"(f));
    return r;
}

__device__ __forceinline__ void st_tf32_4(uint32_t* d, float4 v) {
    uint4 u;
    u.x = f2tf32(v.x); u.y = f2tf32(v.y); u.z = f2tf32(v.z); u.w = f2tf32(v.w);
    *(uint4*)d = u;
}

__device__ __forceinline__ void mma_tf32(float c[4],
                                         uint32_t a0, uint32_t a1, uint32_t a2, uint32_t a3,
                                         uint32_t b0, uint32_t b1) {
    asm volatile(
        "mma.sync.aligned.m16n8k8.row.col.f32.tf32.tf32.f32 "
        "{%0,%1,%2,%3}, {%4,%5,%6,%7}, {%8,%9}, {%0,%1,%2,%3};\n"
        : "+f"(c[0]), "+f"(c[1]), "+f"(c[2]), "+f"(c[3])
        : "r"(a0), "r"(a1), "r"(a2), "r"(a3), "r"(b0), "r"(b1));
}

__device__ __forceinline__ float sigf(float x) {
    return 1.0f / (1.0f + expf(-x));
}

__device__ __forceinline__ void cpa16(void* dst_smem, const void* src_glob) {
    uint32_t d = (uint32_t)__cvta_generic_to_shared(dst_smem);
    asm volatile("cp.async.cg.shared.global [%0], [%1], 16;\n" :: "r"(d), "l"(src_glob));
}
#define CP_COMMIT() asm volatile("cp.async.commit_group;\n" ::: "memory")
#define CP_WAIT1()  asm volatile("cp.async.wait_group 1;\n" ::: "memory")

__device__ __forceinline__ void pfL2(const void* p) {
    asm volatile("prefetch.global.L2 [%0];\n" :: "l"(p));
}

// ---------------- init state ---------------------------------------------
__global__ void init_state(const float* __restrict__ c0,
                           const float* __restrict__ h0,
                           const unsigned char* __restrict__ eos0) {
    int i = blockIdx.x * blockDim.x + threadIdx.x;
    if (i < BATCH * HDIM) {
        g_c[0][i] = c0[i];
        g_h[0][i] = h0[i];
    }
    if (i < BATCH) g_eos[0][i] = eos0[i] ? 1 : 0;
    if (i == 0) { g_bar_count = 0; g_bar_gen = 0; }
}

// ---------------- phase 1: gates_x = X @ Wi + b  (round-4 proven) ----------
#define G1_BM 128
#define G1_BN 128
#define G1_BK 16
#define G1_ASTR 20
#define G1_BSTR 132

__global__ __launch_bounds__(256) void gemm1(const float* __restrict__ X,
                                             const float* __restrict__ Wi,
                                             const float* __restrict__ bias) {
    __shared__ uint32_t As[2][G1_BM * G1_ASTR];
    __shared__ uint32_t Bs[2][G1_BK * G1_BSTR];

    const int tid  = threadIdx.x;
    const int lane = tid & 31;
    const int wid  = tid >> 5;
    const int wm   = (wid >> 1) * 32;
    const int wn   = (wid & 1) * 64;
    const int lq   = lane >> 2;
    const int lr   = lane & 3;

    const int m0 = blockIdx.y * G1_BM;
    const int n0 = blockIdx.x * G1_BN;

    float acc[2][8][4];
#pragma unroll
    for (int mi = 0; mi < 2; mi++)
#pragma unroll
        for (int ni = 0; ni < 8; ni++)
#pragma unroll
            for (int q = 0; q < 4; q++) acc[mi][ni][q] = 0.0f;

    const int ar = tid >> 1;
    const int ac = (tid & 1) * 8;
    const int br = tid >> 4;
    const int bc = (tid & 15) * 8;

    const float* asrc = X  + (size_t)(m0 + ar) * VDIM + ac;
    const float* bsrc = Wi + (size_t)br * GDIM + n0 + bc;

    float4 av0 = *(const float4*)(asrc);
    float4 av1 = *(const float4*)(asrc + 4);
    float4 bv0 = *(const float4*)(bsrc);
    float4 bv1 = *(const float4*)(bsrc + 4);

    const int NIT = VDIM / G1_BK;   // 128
    for (int it = 0; it < NIT; it++) {
        const int p = it & 1;
        st_tf32_4(&As[p][ar * G1_ASTR + ac],     av0);
        st_tf32_4(&As[p][ar * G1_ASTR + ac + 4], av1);
        st_tf32_4(&Bs[p][br * G1_BSTR + bc],     bv0);
        st_tf32_4(&Bs[p][br * G1_BSTR + bc + 4], bv1);
        __syncthreads();

        if (it + 1 < NIT) {
            int k1 = (it + 1) * G1_BK;
            av0 = *(const float4*)(asrc + k1);
            av1 = *(const float4*)(asrc + k1 + 4);
            bv0 = *(const float4*)(bsrc + (size_t)k1 * GDIM);
            bv1 = *(const float4*)(bsrc + (size_t)k1 * GDIM + 4);
        }

        const uint32_t* as = As[p];
        const uint32_t* bs = Bs[p];
#pragma unroll
        for (int kk = 0; kk < G1_BK; kk += 8) {
            uint32_t afr[2][4];
#pragma unroll
            for (int mi = 0; mi < 2; mi++) {
                int r = wm + mi * 16 + lq;
                afr[mi][0] = as[r * G1_ASTR + kk + lr];
                afr[mi][1] = as[(r + 8) * G1_ASTR + kk + lr];
                afr[mi][2] = as[r * G1_ASTR + kk + lr + 4];
                afr[mi][3] = as[(r + 8) * G1_ASTR + kk + lr + 4];
            }
            uint32_t bfr[8][2];
#pragma unroll
            for (int ni = 0; ni < 8; ni++) {
                int c = wn + ni * 8 + lq;
                bfr[ni][0] = bs[(kk + lr) * G1_BSTR + c];
                bfr[ni][1] = bs[(kk + lr + 4) * G1_BSTR + c];
            }
#pragma unroll
            for (int mi = 0; mi < 2; mi++)
#pragma unroll
                for (int ni = 0; ni < 8; ni++)
                    mma_tf32(acc[mi][ni], afr[mi][0], afr[mi][1], afr[mi][2], afr[mi][3],
                             bfr[ni][0], bfr[ni][1]);
        }
    }

#pragma unroll
    for (int mi = 0; mi < 2; mi++) {
#pragma unroll
        for (int ni = 0; ni < 8; ni++) {
            int r0 = m0 + wm + mi * 16 + lq;
            int c0 = n0 + wn + ni * 8 + 2 * lr;
            float bl = bias[c0];
            float bh = bias[c0 + 1];
            g_gates[(size_t)r0 * GDIM + c0]           = acc[mi][ni][0] + bl;
            g_gates[(size_t)r0 * GDIM + c0 + 1]       = acc[mi][ni][1] + bh;
            g_gates[(size_t)(r0 + 8) * GDIM + c0]     = acc[mi][ni][2] + bl;
            g_gates[(size_t)(r0 + 8) * GDIM + c0 + 1] = acc[mi][ni][3] + bh;
        }
    }
}

// ---------------- phase 2: persistent recurrent kernel ---------------------
// R8 pipeline + 8 warps (4M x 2N warp grid, 2 gates/warp), smem gate
// exchange, flat 512-output cell epilogue, L2 prefetch of gate operands.
#define NSTG 3
#define WS_STR 36
#define HS_STR 36
#define GS_STR 34
#define WS_WORDS (HDIM * WS_STR)                // 36864
#define HS_WORDS (NSTG * BATCH * HS_STR)        // 6912
#define GS_WORDS (BATCH * GS_STR)               // 2176
#define PSMEM_BYTES ((WS_WORDS + HS_WORDS + GS_WORDS) * 4) // 183808 B

__device__ __forceinline__ void grid_barrier() {
    __syncthreads();
    if (threadIdx.x == 0) {
        __threadfence();
        unsigned gen = g_bar_gen;
        unsigned t = atomicAdd(&g_bar_count, 1u);
        if (t == NCTA - 1) {
            g_bar_count = 0;
            __threadfence();
            g_bar_gen = gen + 1;
        } else {
            while (g_bar_gen == gen) { }
            __threadfence();
        }
    }
    __syncthreads();
}

__global__ __launch_bounds__(NTHR) void lstm_persist(const float* __restrict__ X,
                                                     const float* __restrict__ Wh,
                                                     float* __restrict__ ys) {
    extern __shared__ uint32_t dsm[];
    uint32_t* ws  = dsm;                       // [1024][36] Wh slice (tf32)
    float*    hs  = (float*)(dsm + WS_WORDS);  // [3][64][36] h tiles (float)
    float*    gsm = (float*)(dsm + WS_WORDS + HS_WORDS); // [64][34] gate sums

    const int tid  = threadIdx.x;
    const int lane = tid & 31;
    const int w    = tid >> 5;        // warp 0..7
    const int lq   = lane >> 2;
    const int lr   = lane & 3;
    const int j    = blockIdx.x;      // hidden slice

    const int wm16 = (w >> 1) * 16;   // M offset: 4 splits of 16 rows
    const int wn   = w & 1;           // N half: gates {0,1} or {2,3}

    // ---- preload Wh slice into SMEM once (converted to tf32) ----
    // 256 threads: wk=tid>>3 (0..31 rows/chunk), q=tid&7 -> one float4 each
    {
        const int wk = tid >> 3;
        const int q  = tid & 7;
        const int g  = q >> 1;
        const int half = q & 1;
        for (int base = 0; base < HDIM; base += 32) {
            float4 v = *(const float4*)(Wh + (size_t)(base + wk) * GDIM + g * HDIM + j * 8 + half * 4);
            st_tf32_4(ws + (base + wk) * WS_STR + q * 4, v);
        }
    }
    __syncthreads();

    // h staging map: 256 threads, row = tid>>2 (0..63), slot = tid&3 (8 floats)
    const int hr = tid >> 2;
    const int hc = (tid & 3) * 8;
    const int NIT = HDIM / 32;        // 32 k-tiles per step

    for (int t = 0; t < T_STEPS; t++) {
        const int cur = t & 1;
        const int nxt = cur ^ 1;
        const float* hprev = g_h[cur];
        const float* cprev = g_c[cur];
        float* hnex = g_h[nxt];
        float* cnex = g_c[nxt];
        const float* gx = g_gates + (size_t)t * BATCH * GDIM;

        // ---- L2 prefetch of this step's epilogue gate operands ----
#pragma unroll
        for (int pass = 0; pass < 2; pass++) {
            int idx = tid + pass * NTHR;       // 0..511
            int r = idx >> 3, u = idx & 7;
            const float* gp = gx + (size_t)r * GDIM + j * 8 + u;
            pfL2(gp);
            pfL2(gp + HDIM);
            pfL2(gp + 2 * HDIM);
            pfL2(gp + 3 * HDIM);
        }

        float acc[2][4];                       // [ni][frag], 2 gate cols of 8
#pragma unroll
        for (int ni = 0; ni < 2; ni++)
#pragma unroll
            for (int q = 0; q < 4; q++) acc[ni][q] = 0.0f;

        // ---- cp.async pipeline prologue: stages 0 and 1 ----
#pragma unroll
        for (int s = 0; s < 2; s++) {
            float* hb = hs + s * (BATCH * HS_STR);
            cpa16(hb + hr * HS_STR + hc,     hprev + (size_t)hr * HDIM + s * 32 + hc);
            cpa16(hb + hr * HS_STR + hc + 4, hprev + (size_t)hr * HDIM + s * 32 + hc + 4);
            CP_COMMIT();
        }

        for (int it = 0; it < NIT; it++) {
            CP_WAIT1();
            __syncthreads();

            if (it + 2 < NIT) {
                float* hb2 = hs + ((it + 2) % NSTG) * (BATCH * HS_STR);
                cpa16(hb2 + hr * HS_STR + hc,     hprev + (size_t)hr * HDIM + (it + 2) * 32 + hc);
                cpa16(hb2 + hr * HS_STR + hc + 4, hprev + (size_t)hr * HDIM + (it + 2) * 32 + hc + 4);
            }
            CP_COMMIT();

            const float* hb = hs + (it % NSTG) * (BATCH * HS_STR);
            const int k0 = it * 32;
#pragma unroll
            for (int kk = 0; kk < 32; kk += 8) {
                int r = wm16 + lq;
                uint32_t a0 = f2tf32(hb[r * HS_STR + kk + lr]);
                uint32_t a1 = f2tf32(hb[(r + 8) * HS_STR + kk + lr]);
                uint32_t a2 = f2tf32(hb[r * HS_STR + kk + lr + 4]);
                uint32_t a3 = f2tf32(hb[(r + 8) * HS_STR + kk + lr + 4]);
#pragma unroll
                for (int ni = 0; ni < 2; ni++) {
                    int g = wn * 2 + ni;       // gate 0..3
                    uint32_t b0 = ws[(k0 + kk + lr) * WS_STR + g * 8 + lq];
                    uint32_t b1 = ws[(k0 + kk + lr + 4) * WS_STR + g * 8 + lq];
                    mma_tf32(acc[ni], a0, a1, a2, a3, b0, b1);
                }
            }
        }

        // ---- exchange: dump warp accumulators to gsm[64][34] ----
#pragma unroll
        for (int ni = 0; ni < 2; ni++) {
            int col = (wn * 2 + ni) * 8 + 2 * lr;
            int row = wm16 + lq;
            gsm[row * GS_STR + col]           = acc[ni][0];
            gsm[row * GS_STR + col + 1]       = acc[ni][1];
            gsm[(row + 8) * GS_STR + col]     = acc[ni][2];
            gsm[(row + 8) * GS_STR + col + 1] = acc[ni][3];
        }
        __syncthreads();

        // ---- cell epilogue: 512 outputs over 256 threads ----
#pragma unroll
        for (int pass = 0; pass < 2; pass++) {
            int idx = tid + pass * NTHR;       // 0..511
            int r = idx >> 3, u = idx & 7;
            int hcol = j * 8 + u;

            bool m = (__ldcg(&g_eos[cur][r]) != 0);
            const float* gp = gx + (size_t)r * GDIM + hcol;
            float iv = gsm[r * GS_STR + u]      + __ldg(gp);
            float fv = gsm[r * GS_STR + 8 + u]  + __ldg(gp + HDIM);
            float gv = gsm[r * GS_STR + 16 + u] + __ldg(gp + 2 * HDIM);
            float ov = gsm[r * GS_STR + 24 + u] + __ldg(gp + 3 * HDIM);

            float cp  = __ldcg(cprev + (size_t)r * HDIM + hcol);
            float ncv = sigf(fv) * cp + sigf(iv) * tanhf(gv);
            float nhv = sigf(ov) * tanhf(ncv);

            ys[((size_t)t * BATCH + r) * HDIM + hcol] = nhv;   // unmasked
            cnex[(size_t)r * HDIM + hcol] = m ? cp : ncv;
            hnex[(size_t)r * HDIM + hcol] = m ? __ldcg(hprev + (size_t)r * HDIM + hcol) : nhv;
        }

        if (blockIdx.x == 0 && tid < BATCH) {
            float xe = __ldg(X + ((size_t)t * BATCH + tid) * VDIM + 1);
            int eo = __ldcg(&g_eos[cur][tid]);
            g_eos[nxt][tid] = (eo != 0 || xe != 0.0f) ? 1 : 0;
        }

        __threadfence();
        grid_barrier();   // also protects gsm reuse next step
    }
}

// ---------------- launch ---------------------------------------------------
extern "C" void kernel_launch(void* const* d_in, const int* in_sizes, int n_in,
                              void* d_out, int out_size) {
    const float* x  = (const float*)d_in[0];
    const float* Wi = (const float*)d_in[1];
    const float* Wh = (const float*)d_in[2];
    const float* b  = (const float*)d_in[3];
    const float* c0 = (const float*)d_in[4];
    const float* h0 = (const float*)d_in[5];
    const unsigned char* eos0 = (const unsigned char*)d_in[6];
    float* ys = (float*)d_out;

    static bool attr_done = false;
    if (!attr_done) {
        cudaFuncSetAttribute(lstm_persist,
                             cudaFuncAttributeMaxDynamicSharedMemorySize, PSMEM_BYTES);
        attr_done = true;
    }

    init_state<<<(BATCH * HDIM + 255) / 256, 256>>>(c0, h0, eos0);

    dim3 g1(GDIM / G1_BN, (T_STEPS * BATCH) / G1_BM);   // 32 x 64
    gemm1<<<g1, 256>>>(x, Wi, b);

    lstm_persist<<<NCTA, NTHR, PSMEM_BYTES>>>(x, Wh, ys);
}

// round 10
// speedup vs baseline: 2.0254x; 1.0622x over previous
#include <cuda_runtime.h>
#include <cstdint>

#define T_STEPS 128
#define BATCH   64
#define VDIM    2048
#define HDIM    1024
#define GDIM    4096   // 4*H

#define NCTA    128    // persistent CTAs (one per 8 hidden units)
#define NTHR    512    // 16 warps: 4 (M) x 2 (N/gate-pair) x 2 (K-split)

// ---------------- scratch (static device globals; no allocation) ----------
__device__ float g_gates[(size_t)T_STEPS * BATCH * GDIM];  // 134 MB: x@Wi + b
__device__ float g_h[2][BATCH * HDIM];
__device__ float g_c[2][BATCH * HDIM];
__device__ int   g_eos[2][BATCH];
__device__ unsigned g_bar_count;
__device__ volatile unsigned g_bar_gen;

// ---------------- helpers ------------------------------------------------
__device__ __forceinline__ uint32_t f2tf32(float f) {
    uint32_t r;
    asm("cvt.rna.tf32.f32 %0, %1;" : "=r"(r) : "f"(f));
    return r;
}

__device__ __forceinline__ void st_tf32_4(uint32_t* d, float4 v) {
    uint4 u;
    u.x = f2tf32(v.x); u.y = f2tf32(v.y); u.z = f2tf32(v.z); u.w = f2tf32(v.w);
    *(uint4*)d = u;
}

__device__ __forceinline__ void mma_tf32(float c[4],
                                         uint32_t a0, uint32_t a1, uint32_t a2, uint32_t a3,
                                         uint32_t b0, uint32_t b1) {
    asm volatile(
        "mma.sync.aligned.m16n8k8.row.col.f32.tf32.tf32.f32 "
        "{%0,%1,%2,%3}, {%4,%5,%6,%7}, {%8,%9}, {%0,%1,%2,%3};\n"
        : "+f"(c[0]), "+f"(c[1]), "+f"(c[2]), "+f"(c[3])
        : "r"(a0), "r"(a1), "r"(a2), "r"(a3), "r"(b0), "r"(b1));
}

__device__ __forceinline__ float sigf(float x) {
    return 1.0f / (1.0f + expf(-x));
}

__device__ __forceinline__ void cpa16(void* dst_smem, const void* src_glob) {
    uint32_t d = (uint32_t)__cvta_generic_to_shared(dst_smem);
    asm volatile("cp.async.cg.shared.global [%0], [%1], 16;\n" :: "r"(d), "l"(src_glob));
}
#define CP_COMMIT() asm volatile("cp.async.commit_group;\n" ::: "memory")
#define CP_WAIT1()  asm volatile("cp.async.wait_group 1;\n" ::: "memory")

__device__ __forceinline__ void pfL2(const void* p) {
    asm volatile("prefetch.global.L2 [%0];\n" :: "l"(p));
}

// ---------------- init state ---------------------------------------------
__global__ void init_state(const float* __restrict__ c0,
                           const float* __restrict__ h0,
                           const unsigned char* __restrict__ eos0) {
    int i = blockIdx.x * blockDim.x + threadIdx.x;
    if (i < BATCH * HDIM) {
        g_c[0][i] = c0[i];
        g_h[0][i] = h0[i];
    }
    if (i < BATCH) g_eos[0][i] = eos0[i] ? 1 : 0;
    if (i == 0) { g_bar_count = 0; g_bar_gen = 0; }
}

// ---------------- phase 1: gates_x = X @ Wi + b  (round-4 proven) ----------
#define G1_BM 128
#define G1_BN 128
#define G1_BK 16
#define G1_ASTR 20
#define G1_BSTR 132

__global__ __launch_bounds__(256) void gemm1(const float* __restrict__ X,
                                             const float* __restrict__ Wi,
                                             const float* __restrict__ bias) {
    __shared__ uint32_t As[2][G1_BM * G1_ASTR];
    __shared__ uint32_t Bs[2][G1_BK * G1_BSTR];

    const int tid  = threadIdx.x;
    const int lane = tid & 31;
    const int wid  = tid >> 5;
    const int wm   = (wid >> 1) * 32;
    const int wn   = (wid & 1) * 64;
    const int lq   = lane >> 2;
    const int lr   = lane & 3;

    const int m0 = blockIdx.y * G1_BM;
    const int n0 = blockIdx.x * G1_BN;

    float acc[2][8][4];
#pragma unroll
    for (int mi = 0; mi < 2; mi++)
#pragma unroll
        for (int ni = 0; ni < 8; ni++)
#pragma unroll
            for (int q = 0; q < 4; q++) acc[mi][ni][q] = 0.0f;

    const int ar = tid >> 1;
    const int ac = (tid & 1) * 8;
    const int br = tid >> 4;
    const int bc = (tid & 15) * 8;

    const float* asrc = X  + (size_t)(m0 + ar) * VDIM + ac;
    const float* bsrc = Wi + (size_t)br * GDIM + n0 + bc;

    float4 av0 = *(const float4*)(asrc);
    float4 av1 = *(const float4*)(asrc + 4);
    float4 bv0 = *(const float4*)(bsrc);
    float4 bv1 = *(const float4*)(bsrc + 4);

    const int NIT = VDIM / G1_BK;   // 128
    for (int it = 0; it < NIT; it++) {
        const int p = it & 1;
        st_tf32_4(&As[p][ar * G1_ASTR + ac],     av0);
        st_tf32_4(&As[p][ar * G1_ASTR + ac + 4], av1);
        st_tf32_4(&Bs[p][br * G1_BSTR + bc],     bv0);
        st_tf32_4(&Bs[p][br * G1_BSTR + bc + 4], bv1);
        __syncthreads();

        if (it + 1 < NIT) {
            int k1 = (it + 1) * G1_BK;
            av0 = *(const float4*)(asrc + k1);
            av1 = *(const float4*)(asrc + k1 + 4);
            bv0 = *(const float4*)(bsrc + (size_t)k1 * GDIM);
            bv1 = *(const float4*)(bsrc + (size_t)k1 * GDIM + 4);
        }

        const uint32_t* as = As[p];
        const uint32_t* bs = Bs[p];
#pragma unroll
        for (int kk = 0; kk < G1_BK; kk += 8) {
            uint32_t afr[2][4];
#pragma unroll
            for (int mi = 0; mi < 2; mi++) {
                int r = wm + mi * 16 + lq;
                afr[mi][0] = as[r * G1_ASTR + kk + lr];
                afr[mi][1] = as[(r + 8) * G1_ASTR + kk + lr];
                afr[mi][2] = as[r * G1_ASTR + kk + lr + 4];
                afr[mi][3] = as[(r + 8) * G1_ASTR + kk + lr + 4];
            }
            uint32_t bfr[8][2];
#pragma unroll
            for (int ni = 0; ni < 8; ni++) {
                int c = wn + ni * 8 + lq;
                bfr[ni][0] = bs[(kk + lr) * G1_BSTR + c];
                bfr[ni][1] = bs[(kk + lr + 4) * G1_BSTR + c];
            }
#pragma unroll
            for (int mi = 0; mi < 2; mi++)
#pragma unroll
                for (int ni = 0; ni < 8; ni++)
                    mma_tf32(acc[mi][ni], afr[mi][0], afr[mi][1], afr[mi][2], afr[mi][3],
                             bfr[ni][0], bfr[ni][1]);
        }
    }

#pragma unroll
    for (int mi = 0; mi < 2; mi++) {
#pragma unroll
        for (int ni = 0; ni < 8; ni++) {
            int r0 = m0 + wm + mi * 16 + lq;
            int c0 = n0 + wn + ni * 8 + 2 * lr;
            float bl = bias[c0];
            float bh = bias[c0 + 1];
            g_gates[(size_t)r0 * GDIM + c0]           = acc[mi][ni][0] + bl;
            g_gates[(size_t)r0 * GDIM + c0 + 1]       = acc[mi][ni][1] + bh;
            g_gates[(size_t)(r0 + 8) * GDIM + c0]     = acc[mi][ni][2] + bl;
            g_gates[(size_t)(r0 + 8) * GDIM + c0 + 1] = acc[mi][ni][3] + bh;
        }
    }
}

// ---------------- phase 2: persistent recurrent kernel ---------------------
// R9 pipeline + 16 warps (4M x 2N x 2K warp grid). K-split partials summed
// through two gsm buffers in the 1-output-per-thread cell epilogue.
#define NSTG 3
#define WS_STR 36
#define HS_STR 36
#define GS_STR 34
#define WS_WORDS (HDIM * WS_STR)                // 36864
#define HS_WORDS (NSTG * BATCH * HS_STR)        // 6912
#define GS_WORDS (2 * BATCH * GS_STR)           // 4352 (two k-half buffers)
#define PSMEM_BYTES ((WS_WORDS + HS_WORDS + GS_WORDS) * 4) // 192512 B

__device__ __forceinline__ void grid_barrier() {
    __syncthreads();
    if (threadIdx.x == 0) {
        __threadfence();
        unsigned gen = g_bar_gen;
        unsigned t = atomicAdd(&g_bar_count, 1u);
        if (t == NCTA - 1) {
            g_bar_count = 0;
            __threadfence();
            g_bar_gen = gen + 1;
        } else {
            while (g_bar_gen == gen) { }
            __threadfence();
        }
    }
    __syncthreads();
}

__global__ __launch_bounds__(NTHR) void lstm_persist(const float* __restrict__ X,
                                                     const float* __restrict__ Wh,
                                                     float* __restrict__ ys) {
    extern __shared__ uint32_t dsm[];
    uint32_t* ws  = dsm;                       // [1024][36] Wh slice (tf32)
    float*    hs  = (float*)(dsm + WS_WORDS);  // [3][64][36] h tiles (float)
    float*    gsm = (float*)(dsm + WS_WORDS + HS_WORDS); // [2][64][34] partials

    const int tid  = threadIdx.x;
    const int lane = tid & 31;
    const int w    = tid >> 5;        // warp 0..15
    const int lq   = lane >> 2;
    const int lr   = lane & 3;
    const int j    = blockIdx.x;      // hidden slice

    const int kh   = w >> 3;          // k-half: kk in {0,8} or {16,24}
    const int wm16 = ((w >> 1) & 3) * 16;  // M offset: 4 splits of 16 rows
    const int wn   = w & 1;           // N half: gates {0,1} or {2,3}

    // ---- preload Wh slice into SMEM once (converted to tf32) ----
    // 512 threads: row = base + tid>>3 (64 rows/pass), q = tid&7 (one float4)
    {
        const int rr = tid >> 3;
        const int q  = tid & 7;
        const int g  = q >> 1;
        const int half = q & 1;
        for (int base = 0; base < HDIM; base += 64) {
            float4 v = *(const float4*)(Wh + (size_t)(base + rr) * GDIM + g * HDIM + j * 8 + half * 4);
            st_tf32_4(ws + (base + rr) * WS_STR + q * 4, v);
        }
    }
    __syncthreads();

    // h staging map: 512 threads, row = tid>>3 (0..63), 4 floats each
    const int hr = tid >> 3;
    const int hc = (tid & 7) * 4;
    const int NIT = HDIM / 32;        // 32 k-tiles per step

    // epilogue map: one output per thread
    const int er = tid >> 3;          // batch row 0..63
    const int eu = tid & 7;           // hidden unit 0..7

    for (int t = 0; t < T_STEPS; t++) {
        const int cur = t & 1;
        const int nxt = cur ^ 1;
        const float* hprev = g_h[cur];
        const float* cprev = g_c[cur];
        float* hnex = g_h[nxt];
        float* cnex = g_c[nxt];
        const float* gx = g_gates + (size_t)t * BATCH * GDIM;

        // ---- L2 prefetch of this step's epilogue gate operands ----
        {
            const float* gp = gx + (size_t)er * GDIM + j * 8 + eu;
            pfL2(gp);
            pfL2(gp + HDIM);
            pfL2(gp + 2 * HDIM);
            pfL2(gp + 3 * HDIM);
        }

        float acc[2][4];                       // [ni][frag], 2 gate cols of 8
#pragma unroll
        for (int ni = 0; ni < 2; ni++)
#pragma unroll
            for (int q = 0; q < 4; q++) acc[ni][q] = 0.0f;

        // ---- cp.async pipeline prologue: stages 0 and 1 ----
#pragma unroll
        for (int s = 0; s < 2; s++) {
            float* hb = hs + s * (BATCH * HS_STR);
            cpa16(hb + hr * HS_STR + hc, hprev + (size_t)hr * HDIM + s * 32 + hc);
            CP_COMMIT();
        }

        for (int it = 0; it < NIT; it++) {
            CP_WAIT1();
            __syncthreads();

            if (it + 2 < NIT) {
                float* hb2 = hs + ((it + 2) % NSTG) * (BATCH * HS_STR);
                cpa16(hb2 + hr * HS_STR + hc, hprev + (size_t)hr * HDIM + (it + 2) * 32 + hc);
            }
            CP_COMMIT();

            const float* hb = hs + (it % NSTG) * (BATCH * HS_STR);
            const int k0 = it * 32;
#pragma unroll
            for (int ks = 0; ks < 2; ks++) {
                const int kk = kh * 16 + ks * 8;
                int r = wm16 + lq;
                uint32_t a0 = f2tf32(hb[r * HS_STR + kk + lr]);
                uint32_t a1 = f2tf32(hb[(r + 8) * HS_STR + kk + lr]);
                uint32_t a2 = f2tf32(hb[r * HS_STR + kk + lr + 4]);
                uint32_t a3 = f2tf32(hb[(r + 8) * HS_STR + kk + lr + 4]);
#pragma unroll
                for (int ni = 0; ni < 2; ni++) {
                    int g = wn * 2 + ni;       // gate 0..3
                    uint32_t b0 = ws[(k0 + kk + lr) * WS_STR + g * 8 + lq];
                    uint32_t b1 = ws[(k0 + kk + lr + 4) * WS_STR + g * 8 + lq];
                    mma_tf32(acc[ni], a0, a1, a2, a3, b0, b1);
                }
            }
        }

        // ---- exchange: dump warp partials to gsm[kh][64][34] ----
        {
            float* gs = gsm + kh * (BATCH * GS_STR);
#pragma unroll
            for (int ni = 0; ni < 2; ni++) {
                int col = (wn * 2 + ni) * 8 + 2 * lr;
                int row = wm16 + lq;
                gs[row * GS_STR + col]           = acc[ni][0];
                gs[row * GS_STR + col + 1]       = acc[ni][1];
                gs[(row + 8) * GS_STR + col]     = acc[ni][2];
                gs[(row + 8) * GS_STR + col + 1] = acc[ni][3];
            }
        }
        __syncthreads();

        // ---- cell epilogue: one output per thread (512 outputs) ----
        {
            const int r = er, u = eu;
            const int hcol = j * 8 + u;
            const float* g0 = gsm + r * GS_STR;
            const float* g1 = gsm + BATCH * GS_STR + r * GS_STR;

            bool m = (__ldcg(&g_eos[cur][r]) != 0);
            const float* gp = gx + (size_t)r * GDIM + hcol;
            float iv = g0[u]      + g1[u]      + __ldg(gp);
            float fv = g0[8 + u]  + g1[8 + u]  + __ldg(gp + HDIM);
            float gv = g0[16 + u] + g1[16 + u] + __ldg(gp + 2 * HDIM);
            float ov = g0[24 + u] + g1[24 + u] + __ldg(gp + 3 * HDIM);

            float cp  = __ldcg(cprev + (size_t)r * HDIM + hcol);
            float ncv = sigf(fv) * cp + sigf(iv) * tanhf(gv);
            float nhv = sigf(ov) * tanhf(ncv);

            ys[((size_t)t * BATCH + r) * HDIM + hcol] = nhv;   // unmasked
            cnex[(size_t)r * HDIM + hcol] = m ? cp : ncv;
            hnex[(size_t)r * HDIM + hcol] = m ? __ldcg(hprev + (size_t)r * HDIM + hcol) : nhv;
        }

        if (blockIdx.x == 0 && tid < BATCH) {
            float xe = __ldg(X + ((size_t)t * BATCH + tid) * VDIM + 1);
            int eo = __ldcg(&g_eos[cur][tid]);
            g_eos[nxt][tid] = (eo != 0 || xe != 0.0f) ? 1 : 0;
        }

        __threadfence();
        grid_barrier();   // also protects gsm reuse next step
    }
}

// ---------------- launch ---------------------------------------------------
extern "C" void kernel_launch(void* const* d_in, const int* in_sizes, int n_in,
                              void* d_out, int out_size) {
    const float* x  = (const float*)d_in[0];
    const float* Wi = (const float*)d_in[1];
    const float* Wh = (const float*)d_in[2];
    const float* b  = (const float*)d_in[3];
    const float* c0 = (const float*)d_in[4];
    const float* h0 = (const float*)d_in[5];
    const unsigned char* eos0 = (const unsigned char*)d_in[6];
    float* ys = (float*)d_out;

    static bool attr_done = false;
    if (!attr_done) {
        cudaFuncSetAttribute(lstm_persist,
                             cudaFuncAttributeMaxDynamicSharedMemorySize, PSMEM_BYTES);
        attr_done = true;
    }

    init_state<<<(BATCH * HDIM + 255) / 256, 256>>>(c0, h0, eos0);

    dim3 g1(GDIM / G1_BN, (T_STEPS * BATCH) / G1_BM);   // 32 x 64
    gemm1<<<g1, 256>>>(x, Wi, b);

    lstm_persist<<<NCTA, NTHR, PSMEM_BYTES>>>(x, Wh, ys);
}